// round 9
// baseline (speedup 1.0000x reference)
#include <cuda_runtime.h>

// Problem constants (GRUmodule_57105885167750)
#define B_ 2048
#define T_ 512
#define I_ 64
#define G_ 9      // 3*H gates
#define PAD_ 12   // padded gate row (48 B) per (t,b)

typedef unsigned long long ull;

// Scratch: xW0 pre-activations, layout [t][b][12].
// Rows t in [512, 517] are never written by the GEMM and stay zero (static init);
// the scan may prefetch them harmlessly. One extra "dummy" row holds b_ih1 for
// layer-1 lanes so the scan's per-iteration load is select-free and uniform.
#define XW_ROWS (T_ + 6)
#define DUMMY_OFF ((size_t)(T_ + 5) * B_ * PAD_)   // float offset of dummy row region
__device__ float g_xw[(size_t)XW_ROWS * B_ * PAD_];

// ---------------------------------------------------------------------------
// f32x2 packed helpers (FFMA2 etc. are only reachable via PTX)
// ---------------------------------------------------------------------------
__device__ __forceinline__ ull pk(float a, float b) {
    ull r; asm("mov.b64 %0, {%1, %2};" : "=l"(r) : "f"(a), "f"(b)); return r;
}
__device__ __forceinline__ float2 upk(ull v) {
    float2 r; asm("mov.b64 {%0, %1}, %2;" : "=f"(r.x), "=f"(r.y) : "l"(v)); return r;
}
__device__ __forceinline__ ull fma2(ull a, ull b, ull c) {
    ull d; asm("fma.rn.f32x2 %0, %1, %2, %3;" : "=l"(d) : "l"(a), "l"(b), "l"(c)); return d;
}
__device__ __forceinline__ ull add2(ull a, ull b) {
    ull d; asm("add.rn.f32x2 %0, %1, %2;" : "=l"(d) : "l"(a), "l"(b)); return d;
}
__device__ __forceinline__ float ex2f(float x) {
    float y; asm("ex2.approx.f32 %0, %1;" : "=f"(y) : "f"(x)); return y;
}
__device__ __forceinline__ float rcpf(float x) {
    float y; asm("rcp.approx.f32 %0, %1;" : "=f"(y) : "f"(x)); return y;
}
// sigma(x) = 1/(1+2^(-x*log2e)); overflow-safe both directions (rcp(inf)=0).
__device__ __forceinline__ float fsig(float x) {
    return rcpf(1.0f + ex2f(x * -1.442695041f));
}
// tanh(y) = 2*sigma(2y) - 1
__device__ __forceinline__ float ftanh(float y) {
    return fmaf(2.0f, rcpf(1.0f + ex2f(y * -2.885390082f)), -1.0f);
}

// ---------------------------------------------------------------------------
// Init kernel: write b_ih1 into the dummy row (layer-1 lanes read it each step)
// ---------------------------------------------------------------------------
__global__ void init_dummy_kernel(const float* __restrict__ bih1) {
    int t = threadIdx.x;
    if (t < PAD_) g_xw[DUMMY_OFF + t] = (t < G_) ? bih1[t] : 0.0f;
}

// ---------------------------------------------------------------------------
// Kernel A: xW0[t,b,:] = b_ih0 + x[b,t,:] @ W_ih0^T   (t-major row order)
// Block = 128 threads at fixed t; thread handles batches (b, b+1) paired into
// f32x2 lanes -> FFMA2. Stores are fully coalesced ([t][b][12] contiguous in b).
// x reads: each lane reads 256 B contiguous (full-line utilization).
// ---------------------------------------------------------------------------
__global__ __launch_bounds__(128, 2) void xw_gemm_kernel(
    const float* __restrict__ x,
    const float* __restrict__ Wih0,
    const float* __restrict__ bih0)
{
    __shared__ float2 wd[G_ * I_];   // dup-packed weights (w,w), 9x64
    __shared__ float2 bd[G_];        // dup-packed bias

    const int tid = threadIdx.x;
    const int t  = blockIdx.x >> 3;          // 512 t values
    const int b  = ((blockIdx.x & 7) << 8) + 2 * tid;   // 8 blocks of 256 b per t

    for (int i = tid; i < G_ * I_; i += 128) {
        float w = Wih0[i];
        wd[i] = make_float2(w, w);
    }
    if (tid < G_) { float v = bih0[tid]; bd[tid] = make_float2(v, v); }
    __syncthreads();

    const float4* xA = (const float4*)(x + ((size_t)b * T_ + t) * I_);
    const float4* xB = (const float4*)(x + ((size_t)(b + 1) * T_ + t) * I_);

    ull acc[G_];
#pragma unroll
    for (int j = 0; j < G_; j++) acc[j] = *(const ull*)&bd[j];

#pragma unroll 4
    for (int u = 0; u < 16; u++) {
        float4 a4 = xA[u];
        float4 b4 = xB[u];
        ull xp0 = pk(a4.x, b4.x);
        ull xp1 = pk(a4.y, b4.y);
        ull xp2 = pk(a4.z, b4.z);
        ull xp3 = pk(a4.w, b4.w);
#pragma unroll
        for (int j = 0; j < G_; j++) {
            const ull* wp = (const ull*)&wd[j * I_ + u * 4];   // (w,w) pairs k..k+3
            ull w01_0 = wp[0], w01_1 = wp[1], w01_2 = wp[2], w01_3 = wp[3];
            acc[j] = fma2(xp0, w01_0, acc[j]);
            acc[j] = fma2(xp1, w01_1, acc[j]);
            acc[j] = fma2(xp2, w01_2, acc[j]);
            acc[j] = fma2(xp3, w01_3, acc[j]);
        }
    }

    float2 v[G_];
#pragma unroll
    for (int j = 0; j < G_; j++) v[j] = upk(acc[j]);

    float* dA = g_xw + ((size_t)t * B_ + b) * PAD_;
    *(float4*)(dA)      = make_float4(v[0].x, v[1].x, v[2].x, v[3].x);
    *(float4*)(dA + 4)  = make_float4(v[4].x, v[5].x, v[6].x, v[7].x);
    *(float4*)(dA + 8)  = make_float4(v[8].x, 0.f, 0.f, 0.f);
    float* dB = dA + PAD_;
    *(float4*)(dB)      = make_float4(v[0].y, v[1].y, v[2].y, v[3].y);
    *(float4*)(dB + 4)  = make_float4(v[4].y, v[5].y, v[6].y, v[7].y);
    *(float4*)(dB + 8)  = make_float4(v[8].y, 0.f, 0.f, 0.f);
}

// ---------------------------------------------------------------------------
// Kernel B: fused two-layer GRU scan, select-free main loop.
// Lanes 0..15: layer 0 (batches b..b+15); lanes 16..31: layer 1, one step
// behind, same batches. Layer-0 lanes carry W_ih == 0; layer-1 lanes read a
// fixed dummy row (= b_ih1) with pointer stride 0 -> uniform code, no sels.
// Gate math pair-packed into f32x2 (memory pairs are free via ulonglong2).
// Note: at it=512, layer-0 lanes consume the all-zero row t=512 and compute a
// bogus h update — harmless: nothing downstream consumes it (layer-0 lanes
// never store; the last shfl'd p is unused by layer-1's final real step).
// ---------------------------------------------------------------------------
__global__ __launch_bounds__(32) void gru_scan_kernel(
    const float* __restrict__ Whh0g, const float* __restrict__ bhh0g,
    const float* __restrict__ Wih1g, const float* __restrict__ Whh1g,
    const float* __restrict__ bhh1g,
    float* __restrict__ out)
{
    const int lane = threadIdx.x;
    const bool is0 = (lane < 16);
    const int b = blockIdx.x * 16 + (lane & 15);

    // ---- pack weights into f32x2 gate-pairs (registers) ----
    const float* Whh = is0 ? Whh0g : Whh1g;
    const float* bhh = is0 ? bhh0g : bhh1g;
    ull Wih2[5][3], Whh2[5][3], bhh2[5];
#pragma unroll
    for (int p = 0; p < 4; p++) {
#pragma unroll
        for (int k = 0; k < 3; k++) {
            Wih2[p][k] = is0 ? pk(0.f, 0.f)
                             : pk(Wih1g[(2*p)*3 + k], Wih1g[(2*p+1)*3 + k]);
            Whh2[p][k] = pk(Whh[(2*p)*3 + k], Whh[(2*p+1)*3 + k]);
        }
        bhh2[p] = pk(bhh[2*p], bhh[2*p+1]);
    }
#pragma unroll
    for (int k = 0; k < 3; k++) {
        Wih2[4][k] = is0 ? pk(0.f, 0.f) : pk(Wih1g[24 + k], 0.f);
        Whh2[4][k] = pk(Whh[24 + k], 0.f);
    }
    bhh2[4] = pk(bhh[8], 0.f);

    float h0 = 0.f, h1 = 0.f, h2 = 0.f;
    float p0 = 0.f, p1 = 0.f, p2 = 0.f;

    // per-lane row pointer: layer0 walks t rows; layer1 sits on the dummy row
    const char* ptr = (const char*)g_xw
        + (is0 ? (size_t)b * (PAD_ * 4) : DUMMY_OFF * 4);
    const long long stride = is0 ? (long long)B_ * PAD_ * 4 : 0;

    // depth-2 prefetch buffers (pairs come straight from the 16B loads)
    ulonglong2 bA[2], bB[2];
    ull bC[2];
    bA[0] = *(const ulonglong2*)(ptr);
    bB[0] = *(const ulonglong2*)(ptr + 16);
    bC[0] = *(const ull*)(ptr + 32);
    ptr += stride;
    bA[1] = *(const ulonglong2*)(ptr);
    bB[1] = *(const ulonglong2*)(ptr + 16);
    bC[1] = *(const ull*)(ptr + 32);
    ptr += stride;

#define BODY(d)                                                                 \
    do {                                                                        \
        ulonglong2 A0 = bA[d], A1 = bB[d];                                      \
        ull A2 = bC[d];                                                         \
        bA[d] = *(const ulonglong2*)(ptr);                                      \
        bB[d] = *(const ulonglong2*)(ptr + 16);                                 \
        bC[d] = *(const ull*)(ptr + 32);                                        \
        ptr += stride;                                                          \
        ull hh0 = pk(h0, h0), hh1 = pk(h1, h1), hh2 = pk(h2, h2);               \
        ull pp0 = pk(p0, p0), pp1 = pk(p1, p1), pp2 = pk(p2, p2);               \
        ull gA = fma2(hh2, Whh2[0][2], fma2(hh1, Whh2[0][1], fma2(hh0, Whh2[0][0], bhh2[0]))); \
        ull gB = fma2(hh2, Whh2[1][2], fma2(hh1, Whh2[1][1], fma2(hh0, Whh2[1][0], bhh2[1]))); \
        ull gC = fma2(hh2, Whh2[2][2], fma2(hh1, Whh2[2][1], fma2(hh0, Whh2[2][0], bhh2[2]))); \
        ull gD = fma2(hh2, Whh2[3][2], fma2(hh1, Whh2[3][1], fma2(hh0, Whh2[3][0], bhh2[3]))); \
        ull gE = fma2(hh2, Whh2[4][2], fma2(hh1, Whh2[4][1], fma2(hh0, Whh2[4][0], bhh2[4]))); \
        ull xA_ = fma2(pp2, Wih2[0][2], fma2(pp1, Wih2[0][1], fma2(pp0, Wih2[0][0], A0.x)));  \
        ull xB_ = fma2(pp2, Wih2[1][2], fma2(pp1, Wih2[1][1], fma2(pp0, Wih2[1][0], A0.y)));  \
        ull xC_ = fma2(pp2, Wih2[2][2], fma2(pp1, Wih2[2][1], fma2(pp0, Wih2[2][0], A1.x)));  \
        ull xD_ = fma2(pp2, Wih2[3][2], fma2(pp1, Wih2[3][1], fma2(pp0, Wih2[3][0], A1.y)));  \
        ull xE_ = fma2(pp2, Wih2[4][2], fma2(pp1, Wih2[4][1], fma2(pp0, Wih2[4][0], A2)));    \
        float2 S0 = upk(add2(xA_, gA));  /* (r0, r1) pre-acts */                \
        float2 S1 = upk(add2(xB_, gB));  /* (r2, z0) */                         \
        float2 S2 = upk(add2(xC_, gC));  /* (z1, z2) */                         \
        float2 X3 = upk(xD_), G3 = upk(gD);  /* gates 6,7 = n0, n1 */           \
        float2 X4 = upk(xE_), G4 = upk(gE);  /* gate 8 = n2 */                  \
        float r0 = fsig(S0.x), r1 = fsig(S0.y), r2 = fsig(S1.x);                \
        float z0 = fsig(S1.y), z1 = fsig(S2.x), z2 = fsig(S2.y);                \
        float n0 = ftanh(fmaf(r0, G3.x, X3.x));                                 \
        float n1 = ftanh(fmaf(r1, G3.y, X3.y));                                 \
        float n2 = ftanh(fmaf(r2, G4.x, X4.x));                                 \
        h0 = fmaf(z0, h0 - n0, n0);                                             \
        h1 = fmaf(z1, h1 - n1, n1);                                             \
        h2 = fmaf(z2, h2 - n2, n2);                                             \
        p0 = __shfl_sync(0xffffffffu, h0, lane & 15);                           \
        p1 = __shfl_sync(0xffffffffu, h1, lane & 15);                           \
        p2 = __shfl_sync(0xffffffffu, h2, lane & 15);                           \
    } while (0)

    // it = 0 peel: only layer 0's update is real; reset layer-1 h afterwards.
    BODY(0);
    h0 = is0 ? h0 : 0.f;
    h1 = is0 ? h1 : 0.f;
    h2 = is0 ? h2 : 0.f;

    // main loop: it = 1..512, both halves unconditionally active.
    // layer0 consumes row t=it (row 512 is zero & discarded at it=512);
    // layer1 consumes timestep t=it-1 via p from the previous shfl.
#pragma unroll 2
    for (int it = 1; it <= 512; it++) {
        BODY(it & 1);
    }
#undef BODY

    if (!is0) {
        float* o = out + (size_t)b * 3;
        o[0] = h0; o[1] = h1; o[2] = h2;
    }
}

// ---------------------------------------------------------------------------
// Launch.  d_in: 0=x 1=W_ih0 2=W_hh0 3=b_ih0 4=b_hh0 5=W_ih1 6=W_hh1 7=b_ih1 8=b_hh1
// ---------------------------------------------------------------------------
extern "C" void kernel_launch(void* const* d_in, const int* in_sizes, int n_in,
                              void* d_out, int out_size)
{
    const float* x    = (const float*)d_in[0];
    const float* Wih0 = (const float*)d_in[1];
    const float* Whh0 = (const float*)d_in[2];
    const float* bih0 = (const float*)d_in[3];
    const float* bhh0 = (const float*)d_in[4];
    const float* Wih1 = (const float*)d_in[5];
    const float* Whh1 = (const float*)d_in[6];
    const float* bih1 = (const float*)d_in[7];
    const float* bhh1 = (const float*)d_in[8];
    float* out = (float*)d_out;

    init_dummy_kernel<<<1, 32>>>(bih1);
    xw_gemm_kernel<<<(B_ / 256) * T_, 128>>>(x, Wih0, bih0);      // 4096 blocks
    gru_scan_kernel<<<B_ / 16, 32>>>(Whh0, bhh0, Wih1, Whh1, bhh1, out);
}

// round 12
// speedup vs baseline: 1.1221x; 1.1221x over previous
#include <cuda_runtime.h>

// Problem constants (GRUmodule_57105885167750)
#define B_ 2048
#define T_ 512
#define I_ 64
#define G_ 9      // 3*H gates
#define BP_ 2056  // padded batch stride of the xw tensor (>= 2051, nice alignment)
#define ROWF_ 12  // floats per (t,b) row: 3 components x float4(r,z,n,pad)

typedef unsigned long long ull;

// Scratch: xW0 pre-activations, layout [t][b][j][4] with b-stride BP_.
// f4(t,b,j) = (xr_j, xz_j, xn_j, 0).  Rows t in [512,516] stay zero (static
// init) for harmless prefetch; row t=517,b=0 is the "dummy" row holding b_ih1
// re-grouped the same way, read by layer-1 lanes with pointer stride 0.
#define XW_TROWS 518
#define DUMMY_T 517
__device__ float g_xw[(size_t)XW_TROWS * BP_ * ROWF_];

// ---------------------------------------------------------------------------
// f32x2 helpers (GEMM only) + approx activations
// ---------------------------------------------------------------------------
__device__ __forceinline__ ull pk(float a, float b) {
    ull r; asm("mov.b64 %0, {%1, %2};" : "=l"(r) : "f"(a), "f"(b)); return r;
}
__device__ __forceinline__ float2 upk(ull v) {
    float2 r; asm("mov.b64 {%0, %1}, %2;" : "=f"(r.x), "=f"(r.y) : "l"(v)); return r;
}
__device__ __forceinline__ ull fma2(ull a, ull b, ull c) {
    ull d; asm("fma.rn.f32x2 %0, %1, %2, %3;" : "=l"(d) : "l"(a), "l"(b), "l"(c)); return d;
}
__device__ __forceinline__ float ex2f(float x) {
    float y; asm("ex2.approx.f32 %0, %1;" : "=f"(y) : "f"(x)); return y;
}
__device__ __forceinline__ float rcpf(float x) {
    float y; asm("rcp.approx.f32 %0, %1;" : "=f"(y) : "f"(x)); return y;
}
// sigma(x); overflow-safe both directions (rcp(inf)=0)
__device__ __forceinline__ float fsig(float x) {
    return rcpf(1.0f + ex2f(x * -1.442695041f));
}
// tanh(y) = 2*sigma(2y) - 1
__device__ __forceinline__ float ftanh(float y) {
    return fmaf(2.0f, rcpf(1.0f + ex2f(y * -2.885390082f)), -1.0f);
}

// ---------------------------------------------------------------------------
// Kernel A: xW0 = b_ih0 + x @ W_ih0^T, written component-grouped [t][b][j][4].
// Same structure as R9 (t-major, coalesced stores, f32x2 FMA); epilogue
// regroups gates by component; block 0 additionally writes the dummy row.
// ---------------------------------------------------------------------------
__global__ __launch_bounds__(128, 2) void xw_gemm_kernel(
    const float* __restrict__ x,
    const float* __restrict__ Wih0,
    const float* __restrict__ bih0,
    const float* __restrict__ bih1)
{
    __shared__ float2 wd[G_ * I_];   // dup-packed weights (w,w)
    __shared__ float2 bd[G_];

    const int tid = threadIdx.x;
    const int t  = blockIdx.x >> 3;                     // 512 t values
    const int b  = ((blockIdx.x & 7) << 8) + 2 * tid;   // 8 blocks of 256 b per t

    // dummy row: b_ih1 grouped by component (block 0 only; visible before scan)
    if (blockIdx.x == 0 && tid < 3) {
        float* d = g_xw + ((size_t)DUMMY_T * BP_) * ROWF_ + tid * 4;
        d[0] = bih1[tid]; d[1] = bih1[3 + tid]; d[2] = bih1[6 + tid]; d[3] = 0.f;
    }

    for (int i = tid; i < G_ * I_; i += 128) {
        float w = Wih0[i];
        wd[i] = make_float2(w, w);
    }
    if (tid < G_) { float v = bih0[tid]; bd[tid] = make_float2(v, v); }
    __syncthreads();

    const float4* xA = (const float4*)(x + ((size_t)b * T_ + t) * I_);
    const float4* xB = (const float4*)(x + ((size_t)(b + 1) * T_ + t) * I_);

    ull acc[G_];
#pragma unroll
    for (int j = 0; j < G_; j++) acc[j] = *(const ull*)&bd[j];

#pragma unroll 4
    for (int u = 0; u < 16; u++) {
        float4 a4 = xA[u];
        float4 b4 = xB[u];
        ull xp0 = pk(a4.x, b4.x);
        ull xp1 = pk(a4.y, b4.y);
        ull xp2 = pk(a4.z, b4.z);
        ull xp3 = pk(a4.w, b4.w);
#pragma unroll
        for (int j = 0; j < G_; j++) {
            const ull* wp = (const ull*)&wd[j * I_ + u * 4];
            acc[j] = fma2(xp0, wp[0], acc[j]);
            acc[j] = fma2(xp1, wp[1], acc[j]);
            acc[j] = fma2(xp2, wp[2], acc[j]);
            acc[j] = fma2(xp3, wp[3], acc[j]);
        }
    }

    float2 v[G_];
#pragma unroll
    for (int j = 0; j < G_; j++) v[j] = upk(acc[j]);

    // component-grouped stores: f4_j = (gate j, gate 3+j, gate 6+j, 0)
    float* dA = g_xw + ((size_t)t * BP_ + b) * ROWF_;
    *(float4*)(dA)     = make_float4(v[0].x, v[3].x, v[6].x, 0.f);
    *(float4*)(dA + 4) = make_float4(v[1].x, v[4].x, v[7].x, 0.f);
    *(float4*)(dA + 8) = make_float4(v[2].x, v[5].x, v[8].x, 0.f);
    float* dB = dA + ROWF_;
    *(float4*)(dB)     = make_float4(v[0].y, v[3].y, v[6].y, 0.f);
    *(float4*)(dB + 4) = make_float4(v[1].y, v[4].y, v[7].y, 0.f);
    *(float4*)(dB + 8) = make_float4(v[2].y, v[5].y, v[8].y, 0.f);
}

// ---------------------------------------------------------------------------
// Kernel B: component-split fused two-layer GRU scan.
// 6 lanes per batch: lane = 6q + 3L + j  (q=batch slot 0..4, L=layer, j=comp).
// Each lane holds ONE hidden component -> only 21 weight regs/lane -> NO
// register spills (the R2/R9 killer). Full h and the layer0->layer1 handoff
// come from 6 shfls at loop head. Layer-0 lanes carry Wih=0; layer-1 lanes
// read the fixed dummy row (= b_ih1) with stride 0 -> uniform, select-free.
// Lanes 30,31 + overhanging b compute garbage on zero pad rows, never stored.
// ---------------------------------------------------------------------------
__global__ __launch_bounds__(32) void gru_scan_kernel(
    const float* __restrict__ Whh0g, const float* __restrict__ bhh0g,
    const float* __restrict__ Wih1g, const float* __restrict__ Whh1g,
    const float* __restrict__ bhh1g,
    float* __restrict__ out)
{
    const int lane = threadIdx.x;
    const int q    = lane / 6;          // batch slot (5 for lanes 30,31)
    const int rem  = lane - q * 6;
    const int L    = rem / 3;           // layer 0/1
    const int j    = rem - L * 3;       // hidden component
    const int b    = blockIdx.x * 5 + q;        // <= 2050 < BP_
    const int hs   = lane - j;          // own (batch,layer) trio base
    const int ps   = lane - rem;        // layer-0 trio base (for p)
    const bool is1 = (L == 1);

    // per-lane weights: rows j (r), 3+j (z), 6+j (n)
    const float* Whh = is1 ? Whh1g : Whh0g;
    const float* bhh = is1 ? bhh1g : bhh0g;
    float WR[3], WZ[3], WN[3], UR[3], UZ[3], UN[3];
#pragma unroll
    for (int k = 0; k < 3; k++) {
        WR[k] = Whh[j * 3 + k];
        WZ[k] = Whh[(3 + j) * 3 + k];
        WN[k] = Whh[(6 + j) * 3 + k];
        UR[k] = is1 ? Wih1g[j * 3 + k]       : 0.0f;
        UZ[k] = is1 ? Wih1g[(3 + j) * 3 + k] : 0.0f;
        UN[k] = is1 ? Wih1g[(6 + j) * 3 + k] : 0.0f;
    }
    const float bR = bhh[j], bZ = bhh[3 + j], bN = bhh[6 + j];

    // pointer: layer0 walks t rows; layer1 parked on the dummy row (stride 0)
    const char* ptr = (const char*)g_xw
        + (is1 ? ((size_t)DUMMY_T * BP_) * 48 : (size_t)b * 48) + j * 16;
    const long long stride = is1 ? 0 : (long long)BP_ * 48;

    float4 buf0 = *(const float4*)ptr; ptr += stride;   // t=0
    float4 buf1 = *(const float4*)ptr; ptr += stride;   // t=1

    float h = 0.0f;

#define BODY(BUF)                                                              \
    do {                                                                       \
        float h0 = __shfl_sync(0xffffffffu, h, hs);                            \
        float h1 = __shfl_sync(0xffffffffu, h, hs + 1);                        \
        float h2 = __shfl_sync(0xffffffffu, h, hs + 2);                        \
        float p0 = __shfl_sync(0xffffffffu, h, ps);                            \
        float p1 = __shfl_sync(0xffffffffu, h, ps + 1);                        \
        float p2 = __shfl_sync(0xffffffffu, h, ps + 2);                        \
        float4 f = BUF;                                                        \
        BUF = *(const float4*)ptr; ptr += stride;                              \
        float xr = fmaf(p2, UR[2], fmaf(p1, UR[1], fmaf(p0, UR[0], f.x)));     \
        float xz = fmaf(p2, UZ[2], fmaf(p1, UZ[1], fmaf(p0, UZ[0], f.y)));     \
        float xn = fmaf(p2, UN[2], fmaf(p1, UN[1], fmaf(p0, UN[0], f.z)));     \
        float gr = fmaf(h2, WR[2], fmaf(h1, WR[1], fmaf(h0, WR[0], bR)));      \
        float gz = fmaf(h2, WZ[2], fmaf(h1, WZ[1], fmaf(h0, WZ[0], bZ)));      \
        float gn = fmaf(h2, WN[2], fmaf(h1, WN[1], fmaf(h0, WN[0], bN)));      \
        float r = fsig(xr + gr);                                               \
        float z = fsig(xz + gz);                                               \
        float n = ftanh(fmaf(r, gn, xn));                                      \
        h = fmaf(z, h - n, n);                                                 \
    } while (0)

    // it = 0 peel: layer-0's update (t=0) is real; reset layer-1 h after.
    BODY(buf0);
    if (is1) h = 0.0f;

    // it = 1..512: layer0 consumes t=it (t=512 zero row -> trash update, never
    // consumed); layer1 consumes timestep it-1 via p shuffled at loop head.
    // Max prefetch t = 514 < 517 (dummy). 512 iters = 256 unrolled pairs.
#pragma unroll 1
    for (int it = 0; it < 256; it++) {
        BODY(buf1);
        BODY(buf0);
    }
#undef BODY

    if (is1 && lane < 30 && b < B_) {
        out[b * 3 + j] = h;
    }
}

// ---------------------------------------------------------------------------
// Launch.  d_in: 0=x 1=W_ih0 2=W_hh0 3=b_ih0 4=b_hh0 5=W_ih1 6=W_hh1 7=b_ih1 8=b_hh1
// ---------------------------------------------------------------------------
extern "C" void kernel_launch(void* const* d_in, const int* in_sizes, int n_in,
                              void* d_out, int out_size)
{
    const float* x    = (const float*)d_in[0];
    const float* Wih0 = (const float*)d_in[1];
    const float* Whh0 = (const float*)d_in[2];
    const float* bih0 = (const float*)d_in[3];
    const float* bhh0 = (const float*)d_in[4];
    const float* Wih1 = (const float*)d_in[5];
    const float* Whh1 = (const float*)d_in[6];
    const float* bih1 = (const float*)d_in[7];
    const float* bhh1 = (const float*)d_in[8];
    float* out = (float*)d_out;

    xw_gemm_kernel<<<(B_ / 256) * T_, 128>>>(x, Wih0, bih0, bih1);   // 4096 blocks
    gru_scan_kernel<<<(B_ + 4) / 5, 32>>>(Whh0, bhh0, Wih1, Whh1, bhh1, out);  // 410 blocks
}

// round 14
// speedup vs baseline: 1.3259x; 1.1817x over previous
#include <cuda_runtime.h>

// Problem constants (GRUmodule_57105885167750)
#define B_ 2048
#define T_ 512
#define I_ 64
#define G_ 9      // 3*H gates
#define BP_ 2056  // padded batch stride of the xw tensor (>= 2051, nice alignment)
#define ROWF_ 12  // floats per (t,b) row: 3 components x float4(r,z,n,pad)

typedef unsigned long long ull;

// Scratch: xW0 pre-activations, layout [t][b][j][4] with b-stride BP_.
// f4(t,b,j) = (xr_j, xz_j, xn_j, 0).  Rows t in [512,520] stay zero (static
// init) so the depth-8 prefetch (max t = 512+8 = 520) is harmless; row t=521
// is the "dummy" row holding b_ih1 re-grouped the same way, read by layer-1
// lanes with pointer stride 0.
#define XW_TROWS 522
#define DUMMY_T 521
__device__ float g_xw[(size_t)XW_TROWS * BP_ * ROWF_];

// ---------------------------------------------------------------------------
// f32x2 helpers (GEMM only) + approx activations
// ---------------------------------------------------------------------------
__device__ __forceinline__ ull pk(float a, float b) {
    ull r; asm("mov.b64 %0, {%1, %2};" : "=l"(r) : "f"(a), "f"(b)); return r;
}
__device__ __forceinline__ float2 upk(ull v) {
    float2 r; asm("mov.b64 {%0, %1}, %2;" : "=f"(r.x), "=f"(r.y) : "l"(v)); return r;
}
__device__ __forceinline__ ull fma2(ull a, ull b, ull c) {
    ull d; asm("fma.rn.f32x2 %0, %1, %2, %3;" : "=l"(d) : "l"(a), "l"(b), "l"(c)); return d;
}
__device__ __forceinline__ float ex2f(float x) {
    float y; asm("ex2.approx.f32 %0, %1;" : "=f"(y) : "f"(x)); return y;
}
__device__ __forceinline__ float rcpf(float x) {
    float y; asm("rcp.approx.f32 %0, %1;" : "=f"(y) : "f"(x)); return y;
}
// sigma(x); overflow-safe both directions (rcp(inf)=0)
__device__ __forceinline__ float fsig(float x) {
    return rcpf(1.0f + ex2f(x * -1.442695041f));
}
// tanh(y) = 2*sigma(2y) - 1
__device__ __forceinline__ float ftanh(float y) {
    return fmaf(2.0f, rcpf(1.0f + ex2f(y * -2.885390082f)), -1.0f);
}

// ---------------------------------------------------------------------------
// Kernel A: xW0 = b_ih0 + x @ W_ih0^T, written component-grouped [t][b][j][4].
// t-major, coalesced stores, f32x2 FMA; epilogue regroups gates by component;
// block 0 additionally writes the dummy row. (Unchanged from R12 except the
// dummy-row constant — keeps the round's delta attributable to the scan.)
// ---------------------------------------------------------------------------
__global__ __launch_bounds__(128, 2) void xw_gemm_kernel(
    const float* __restrict__ x,
    const float* __restrict__ Wih0,
    const float* __restrict__ bih0,
    const float* __restrict__ bih1)
{
    __shared__ float2 wd[G_ * I_];   // dup-packed weights (w,w)
    __shared__ float2 bd[G_];

    const int tid = threadIdx.x;
    const int t  = blockIdx.x >> 3;                     // 512 t values
    const int b  = ((blockIdx.x & 7) << 8) + 2 * tid;   // 8 blocks of 256 b per t

    // dummy row: b_ih1 grouped by component (block 0 only; visible before scan)
    if (blockIdx.x == 0 && tid < 3) {
        float* d = g_xw + ((size_t)DUMMY_T * BP_) * ROWF_ + tid * 4;
        d[0] = bih1[tid]; d[1] = bih1[3 + tid]; d[2] = bih1[6 + tid]; d[3] = 0.f;
    }

    for (int i = tid; i < G_ * I_; i += 128) {
        float w = Wih0[i];
        wd[i] = make_float2(w, w);
    }
    if (tid < G_) { float v = bih0[tid]; bd[tid] = make_float2(v, v); }
    __syncthreads();

    const float4* xA = (const float4*)(x + ((size_t)b * T_ + t) * I_);
    const float4* xB = (const float4*)(x + ((size_t)(b + 1) * T_ + t) * I_);

    ull acc[G_];
#pragma unroll
    for (int j = 0; j < G_; j++) acc[j] = *(const ull*)&bd[j];

#pragma unroll 4
    for (int u = 0; u < 16; u++) {
        float4 a4 = xA[u];
        float4 b4 = xB[u];
        ull xp0 = pk(a4.x, b4.x);
        ull xp1 = pk(a4.y, b4.y);
        ull xp2 = pk(a4.z, b4.z);
        ull xp3 = pk(a4.w, b4.w);
#pragma unroll
        for (int j = 0; j < G_; j++) {
            const ull* wp = (const ull*)&wd[j * I_ + u * 4];
            acc[j] = fma2(xp0, wp[0], acc[j]);
            acc[j] = fma2(xp1, wp[1], acc[j]);
            acc[j] = fma2(xp2, wp[2], acc[j]);
            acc[j] = fma2(xp3, wp[3], acc[j]);
        }
    }

    float2 v[G_];
#pragma unroll
    for (int j = 0; j < G_; j++) v[j] = upk(acc[j]);

    // component-grouped stores: f4_j = (gate j, gate 3+j, gate 6+j, 0)
    float* dA = g_xw + ((size_t)t * BP_ + b) * ROWF_;
    *(float4*)(dA)     = make_float4(v[0].x, v[3].x, v[6].x, 0.f);
    *(float4*)(dA + 4) = make_float4(v[1].x, v[4].x, v[7].x, 0.f);
    *(float4*)(dA + 8) = make_float4(v[2].x, v[5].x, v[8].x, 0.f);
    float* dB = dA + ROWF_;
    *(float4*)(dB)     = make_float4(v[0].y, v[3].y, v[6].y, 0.f);
    *(float4*)(dB + 4) = make_float4(v[1].y, v[4].y, v[7].y, 0.f);
    *(float4*)(dB + 8) = make_float4(v[2].y, v[5].y, v[8].y, 0.f);
}

// ---------------------------------------------------------------------------
// Kernel B: component-split fused two-layer GRU scan, DEPTH-8 prefetch.
// 6 lanes per batch: lane = 6q + 3L + j  (q=batch slot 0..4, L=layer, j=comp).
// Each lane holds ONE hidden component -> ~75 live regs -> no spills.
// R12 showed the scan reads g_xw from DRAM (HBM 337 GB/s ~= whole buffer) and
// depth-2 prefetch left ~515 cyc/iter; depth-8 gives an 8*T_iter budget that
// fully covers the ~577-cyc DRAM latency, dropping T_iter to the arithmetic
// chain (~140-170 cyc).
// Layer-0 lanes carry Wih=0; layer-1 lanes read the fixed dummy row (= b_ih1)
// with stride 0 -> uniform, select-free. Lanes 30,31 + overhanging b compute
// garbage on zero pad rows, never stored.
// ---------------------------------------------------------------------------
__global__ __launch_bounds__(32) void gru_scan_kernel(
    const float* __restrict__ Whh0g, const float* __restrict__ bhh0g,
    const float* __restrict__ Wih1g, const float* __restrict__ Whh1g,
    const float* __restrict__ bhh1g,
    float* __restrict__ out)
{
    const int lane = threadIdx.x;
    const int q    = lane / 6;          // batch slot (5 for lanes 30,31)
    const int rem  = lane - q * 6;
    const int L    = rem / 3;           // layer 0/1
    const int j    = rem - L * 3;       // hidden component
    const int b    = blockIdx.x * 5 + q;        // <= 2050 < BP_
    const int hs   = lane - j;          // own (batch,layer) trio base
    const int ps   = lane - rem;        // layer-0 trio base (for p)
    const bool is1 = (L == 1);

    // per-lane weights: rows j (r), 3+j (z), 6+j (n)
    const float* Whh = is1 ? Whh1g : Whh0g;
    const float* bhh = is1 ? bhh1g : bhh0g;
    float WR[3], WZ[3], WN[3], UR[3], UZ[3], UN[3];
#pragma unroll
    for (int k = 0; k < 3; k++) {
        WR[k] = Whh[j * 3 + k];
        WZ[k] = Whh[(3 + j) * 3 + k];
        WN[k] = Whh[(6 + j) * 3 + k];
        UR[k] = is1 ? Wih1g[j * 3 + k]       : 0.0f;
        UZ[k] = is1 ? Wih1g[(3 + j) * 3 + k] : 0.0f;
        UN[k] = is1 ? Wih1g[(6 + j) * 3 + k] : 0.0f;
    }
    const float bR = bhh[j], bZ = bhh[3 + j], bN = bhh[6 + j];

    // pointer: layer0 walks t rows; layer1 parked on the dummy row (stride 0)
    const char* ptr = (const char*)g_xw
        + (is1 ? ((size_t)DUMMY_T * BP_) * 48 : (size_t)b * 48) + j * 16;
    const long long stride = is1 ? 0 : (long long)BP_ * 48;

    // depth-8 prefetch ring: preload t = 0..7
    float4 buf[8];
#pragma unroll
    for (int d = 0; d < 8; d++) {
        buf[d] = *(const float4*)ptr;
        ptr += stride;
    }

    float h = 0.0f;

#define BODY(BUF)                                                              \
    do {                                                                       \
        float h0 = __shfl_sync(0xffffffffu, h, hs);                            \
        float h1 = __shfl_sync(0xffffffffu, h, hs + 1);                        \
        float h2 = __shfl_sync(0xffffffffu, h, hs + 2);                        \
        float p0 = __shfl_sync(0xffffffffu, h, ps);                            \
        float p1 = __shfl_sync(0xffffffffu, h, ps + 1);                        \
        float p2 = __shfl_sync(0xffffffffu, h, ps + 2);                        \
        float4 f = BUF;                                                        \
        BUF = *(const float4*)ptr; ptr += stride;                              \
        float xr = fmaf(p2, UR[2], fmaf(p1, UR[1], fmaf(p0, UR[0], f.x)));     \
        float xz = fmaf(p2, UZ[2], fmaf(p1, UZ[1], fmaf(p0, UZ[0], f.y)));     \
        float xn = fmaf(p2, UN[2], fmaf(p1, UN[1], fmaf(p0, UN[0], f.z)));     \
        float gr = fmaf(h2, WR[2], fmaf(h1, WR[1], fmaf(h0, WR[0], bR)));      \
        float gz = fmaf(h2, WZ[2], fmaf(h1, WZ[1], fmaf(h0, WZ[0], bZ)));      \
        float gn = fmaf(h2, WN[2], fmaf(h1, WN[1], fmaf(h0, WN[0], bN)));      \
        float r = fsig(xr + gr);                                               \
        float z = fsig(xz + gz);                                               \
        float n = ftanh(fmaf(r, gn, xn));                                      \
        h = fmaf(z, h - n, n);                                                 \
    } while (0)

    // it = 0 peel: layer-0's update (t=0) is real; reset layer-1 h after.
    // (BODY(t=0) prefetches t=8 into buf[0].)
    BODY(buf[0]);
    if (is1) h = 0.0f;

    // 512 more BODYs: t = 1..512 in octets buf[1..7,0]. Layer0 consumes t=it
    // (t=512 zero row -> trash update, never consumed); layer1 consumes
    // timestep it-1 via p shuffled at loop head. Max prefetch t = 520 < 521.
#pragma unroll 1
    for (int it = 0; it < 64; it++) {
        BODY(buf[1]);
        BODY(buf[2]);
        BODY(buf[3]);
        BODY(buf[4]);
        BODY(buf[5]);
        BODY(buf[6]);
        BODY(buf[7]);
        BODY(buf[0]);
    }
#undef BODY

    if (is1 && lane < 30 && b < B_) {
        out[b * 3 + j] = h;
    }
}

// ---------------------------------------------------------------------------
// Launch.  d_in: 0=x 1=W_ih0 2=W_hh0 3=b_ih0 4=b_hh0 5=W_ih1 6=W_hh1 7=b_ih1 8=b_hh1
// ---------------------------------------------------------------------------
extern "C" void kernel_launch(void* const* d_in, const int* in_sizes, int n_in,
                              void* d_out, int out_size)
{
    const float* x    = (const float*)d_in[0];
    const float* Wih0 = (const float*)d_in[1];
    const float* Whh0 = (const float*)d_in[2];
    const float* bih0 = (const float*)d_in[3];
    const float* bhh0 = (const float*)d_in[4];
    const float* Wih1 = (const float*)d_in[5];
    const float* Whh1 = (const float*)d_in[6];
    const float* bih1 = (const float*)d_in[7];
    const float* bhh1 = (const float*)d_in[8];
    float* out = (float*)d_out;

    xw_gemm_kernel<<<(B_ / 256) * T_, 128>>>(x, Wih0, bih0, bih1);   // 4096 blocks
    gru_scan_kernel<<<(B_ + 4) / 5, 32>>>(Whh0, bhh0, Wih1, Whh1, bhh1, out);  // 410 blocks
}